// round 7
// baseline (speedup 1.0000x reference)
#include <cuda_runtime.h>
#include <math.h>
#include <stdint.h>

// Problem constants
#define T  8192   // tokens = B*S
#define DM 1024   // model dim
#define EM 8      // experts
#define HM 4096   // hidden dim

// GEMM tiling
#define BM 128
#define BN 64     // ffn1 N-tile (per Wg/Wu)
#define BN2 128   // ffn2 N-tile
#define BK 16
#define PA 4      // A smem pad: stride 20 floats -> conflict-free frag loads
#define PB 8      // B smem pad: stride 72 / 136 floats -> conflict-free frag loads

// Device scratch (static allocation: allowed; cudaMalloc is not)
__device__ int   g_count[EM];
__device__ int   g_tok[EM * T];
__device__ float g_gate[EM * T];
__device__ float g_h[EM * T * HM];   // 1 GiB fp32 (tf32-rounded) hidden activations

// ---------------------------------------------------------------------------
// helpers
// ---------------------------------------------------------------------------
__device__ __forceinline__ uint32_t f2tf32(float x) {
    uint32_t r;
    asm("cvt.rna.tf32.f32 %0, %1;" : "=r"(r) : "f"(x));
    return r;
}

__device__ __forceinline__ void mma_tf32(float d[4], const uint32_t a[4], const uint32_t b[2]) {
    asm volatile(
        "mma.sync.aligned.m16n8k8.row.col.f32.tf32.tf32.f32 "
        "{%0,%1,%2,%3}, {%4,%5,%6,%7}, {%8,%9}, {%0,%1,%2,%3};"
        : "+f"(d[0]), "+f"(d[1]), "+f"(d[2]), "+f"(d[3])
        : "r"(a[0]), "r"(a[1]), "r"(a[2]), "r"(a[3]),
          "r"(b[0]), "r"(b[1]));
}

__device__ __forceinline__ void cp16(void* smem_ptr, const void* gptr, bool valid) {
    uint32_t sa = (uint32_t)__cvta_generic_to_shared(smem_ptr);
    int sz = valid ? 16 : 0;
    asm volatile("cp.async.cg.shared.global [%0], [%1], 16, %2;"
                 :: "r"(sa), "l"(gptr), "r"(sz));
}
__device__ __forceinline__ void cp_commit() { asm volatile("cp.async.commit_group;"); }
template <int N>
__device__ __forceinline__ void cp_wait() { asm volatile("cp.async.wait_group %0;" :: "n"(N)); }

// ---------------------------------------------------------------------------
// zero output + per-expert counters
// ---------------------------------------------------------------------------
__global__ void k_zero(float* __restrict__ out, int n) {
    int i = blockIdx.x * blockDim.x + threadIdx.x;
    if (i < n)  out[i] = 0.0f;
    if (i < EM) g_count[i] = 0;
}

// ---------------------------------------------------------------------------
// router: one warp per token. logits = x @ Wr + br ; top-2 ; softmax(2)
// ---------------------------------------------------------------------------
__global__ void k_router(const float* __restrict__ x,
                         const float* __restrict__ Wr,
                         const float* __restrict__ br) {
    int t    = blockIdx.x * (blockDim.x >> 5) + (threadIdx.x >> 5);
    int lane = threadIdx.x & 31;
    if (t >= T) return;

    const float* xr = x + (size_t)t * DM;
    float acc[EM];
#pragma unroll
    for (int e = 0; e < EM; e++) acc[e] = 0.0f;

    for (int d = lane; d < DM; d += 32) {
        float xv = xr[d];
        const float4 w0 = *(const float4*)(Wr + (size_t)d * EM);
        const float4 w1 = *(const float4*)(Wr + (size_t)d * EM + 4);
        acc[0] += xv * w0.x; acc[1] += xv * w0.y;
        acc[2] += xv * w0.z; acc[3] += xv * w0.w;
        acc[4] += xv * w1.x; acc[5] += xv * w1.y;
        acc[6] += xv * w1.z; acc[7] += xv * w1.w;
    }
#pragma unroll
    for (int e = 0; e < EM; e++) {
#pragma unroll
        for (int o = 16; o > 0; o >>= 1)
            acc[e] += __shfl_xor_sync(0xffffffffu, acc[e], o);
    }

    if (lane == 0) {
        float v[EM];
#pragma unroll
        for (int e = 0; e < EM; e++) v[e] = acc[e] + br[e];

        int b0 = 0; float m0 = v[0];
#pragma unroll
        for (int e = 1; e < EM; e++) if (v[e] > m0) { m0 = v[e]; b0 = e; }
        int b1 = -1; float m1 = -3.4e38f;
#pragma unroll
        for (int e = 0; e < EM; e++) {
            if (e == b0) continue;
            if (v[e] > m1) { m1 = v[e]; b1 = e; }
        }
        float p0 = 1.0f / (1.0f + expf(m1 - m0));  // softmax over {m0, m1}
        float p1 = 1.0f - p0;

        int pos = atomicAdd(&g_count[b0], 1);
        g_tok[b0 * T + pos] = t;  g_gate[b0 * T + pos] = p0;
        pos = atomicAdd(&g_count[b1], 1);
        g_tok[b1 * T + pos] = t;  g_gate[b1 * T + pos] = p1;
    }
}

// ---------------------------------------------------------------------------
// phase 1: h = silu(x @ Wg + bg) * (x @ Wu + bu)   (gathered rows, per expert)
// grid: (T/BM, HM/BN, EM), 256 threads (8 warps, 4x2), warp tile 32x32 dual
// 2-stage cp.async double buffering. 3 CTAs/SM target.
// ---------------------------------------------------------------------------
__global__ __launch_bounds__(256, 3) void k_ffn1(
    const float* __restrict__ x,
    const float* __restrict__ Wg, const float* __restrict__ bg,
    const float* __restrict__ Wu, const float* __restrict__ bu) {

    const int e      = blockIdx.z;
    const int cnt    = g_count[e];
    const int m_base = blockIdx.x * BM;
    if (m_base >= cnt) return;
    const int n_base = blockIdx.y * BN;

    __shared__ float sA [2][BM][BK + PA];
    __shared__ float sBg[2][BK][BN + PB];
    __shared__ float sBu[2][BK][BN + PB];
    __shared__ int   sTok[BM];

    const int tid  = threadIdx.x;
    const int warp = tid >> 5, lane = tid & 31;
    const int g    = lane >> 2, tq  = lane & 3;
    const int wm   = (warp & 3) * 32;
    const int wn   = (warp >> 2) * 32;

    if (tid < BM) {
        int r = m_base + tid;
        sTok[tid] = (r < cnt) ? g_tok[e * T + r] : 0;
    }
    __syncthreads();   // gather loads below read sTok

    float cg[2][4][4], cu[2][4][4];
#pragma unroll
    for (int a = 0; a < 2; a++)
#pragma unroll
        for (int b = 0; b < 4; b++)
#pragma unroll
            for (int c = 0; c < 4; c++) { cg[a][b][c] = 0.0f; cu[a][b][c] = 0.0f; }

    const float* wBg = Wg + (size_t)e * DM * HM + n_base;
    const float* wBu = Wu + (size_t)e * DM * HM + n_base;

    auto load_tiles = [&](int st, int k0) {
        // A: 128 x 16 gathered rows -> 512 float4, 2 per thread
#pragma unroll
        for (int j = 0; j < 2; j++) {
            int idx = tid + j * 256;
            int row = idx >> 2;
            int c4  = (idx & 3) << 2;
            cp16(&sA[st][row][c4], x + (size_t)sTok[row] * DM + (k0 + c4), true);
        }
        // Bg/Bu: 16 x 64 -> 256 float4 each, 1 per thread
        {
            int kr = tid >> 4;
            int c4 = (tid & 15) << 2;
            size_t off = (size_t)(k0 + kr) * HM + c4;
            cp16(&sBg[st][kr][c4], wBg + off, true);
            cp16(&sBu[st][kr][c4], wBu + off, true);
        }
        cp_commit();
    };

    load_tiles(0, 0);
    const int KT = DM / BK;   // 64
    for (int kt = 0; kt < KT; kt++) {
        int cur = kt & 1;
        if (kt + 1 < KT) { load_tiles(cur ^ 1, (kt + 1) * BK); cp_wait<1>(); }
        else             { cp_wait<0>(); }
        __syncthreads();

#pragma unroll
        for (int kk = 0; kk < BK; kk += 8) {
            uint32_t af[2][4];
#pragma unroll
            for (int im = 0; im < 2; im++) {
                int r = wm + im * 16 + g;
                af[im][0] = f2tf32(sA[cur][r    ][kk + tq    ]);
                af[im][1] = f2tf32(sA[cur][r + 8][kk + tq    ]);
                af[im][2] = f2tf32(sA[cur][r    ][kk + tq + 4]);
                af[im][3] = f2tf32(sA[cur][r + 8][kk + tq + 4]);
            }
#pragma unroll
            for (int in = 0; in < 4; in++) {
                int c = wn + in * 8 + g;
                uint32_t bfg[2] = { f2tf32(sBg[cur][kk + tq][c]), f2tf32(sBg[cur][kk + tq + 4][c]) };
                uint32_t bfu[2] = { f2tf32(sBu[cur][kk + tq][c]), f2tf32(sBu[cur][kk + tq + 4][c]) };
#pragma unroll
                for (int im = 0; im < 2; im++) {
                    mma_tf32(cg[im][in], af[im], bfg);
                    mma_tf32(cu[im][in], af[im], bfu);
                }
            }
        }
        __syncthreads();
    }

    // epilogue: bias + silu*up, round to tf32, write h to per-expert slot rows
    float* hb = g_h + (size_t)e * T * HM;
    const float* bge = bg + (size_t)e * HM;
    const float* bue = bu + (size_t)e * HM;
#pragma unroll
    for (int im = 0; im < 2; im++) {
        int r0 = m_base + wm + im * 16 + g;
#pragma unroll
        for (int in = 0; in < 4; in++) {
            int n = n_base + wn + in * 8 + tq * 2;
            float b0g = bge[n], b1g = bge[n + 1];
            float b0u = bue[n], b1u = bue[n + 1];
            if (r0 < cnt) {
                float gv0 = cg[im][in][0] + b0g, uv0 = cu[im][in][0] + b0u;
                float gv1 = cg[im][in][1] + b1g, uv1 = cu[im][in][1] + b1u;
                float2 hv;
                hv.x = __uint_as_float(f2tf32(gv0 / (1.0f + expf(-gv0)) * uv0));
                hv.y = __uint_as_float(f2tf32(gv1 / (1.0f + expf(-gv1)) * uv1));
                *(float2*)(hb + (size_t)r0 * HM + n) = hv;
            }
            if (r0 + 8 < cnt) {
                float gv0 = cg[im][in][2] + b0g, uv0 = cu[im][in][2] + b0u;
                float gv1 = cg[im][in][3] + b1g, uv1 = cu[im][in][3] + b1u;
                float2 hv;
                hv.x = __uint_as_float(f2tf32(gv0 / (1.0f + expf(-gv0)) * uv0));
                hv.y = __uint_as_float(f2tf32(gv1 / (1.0f + expf(-gv1)) * uv1));
                *(float2*)(hb + (size_t)(r0 + 8) * HM + n) = hv;
            }
        }
    }
}

// ---------------------------------------------------------------------------
// phase 2: out[tok] += gate * (h @ Wd + bd)
// grid: (T/BM, DM/BN2, EM), 256 threads (8 warps, 2x4), warp tile 64x32
// 2-stage cp.async double buffering. A (h) is already tf32-rounded -> no cvt.
// 3 CTAs/SM target.
// ---------------------------------------------------------------------------
__global__ __launch_bounds__(256, 3) void k_ffn2(
    const float* __restrict__ Wd, const float* __restrict__ bd,
    float* __restrict__ out) {

    const int e      = blockIdx.z;
    const int cnt    = g_count[e];
    const int m_base = blockIdx.x * BM;
    if (m_base >= cnt) return;
    const int n_base = blockIdx.y * BN2;

    __shared__ float sA[2][BM][BK + PA];       // stride 20
    __shared__ float sB[2][BK][BN2 + PB];      // stride 136
    __shared__ int   sTok[BM];
    __shared__ float sGate[BM];

    const int tid  = threadIdx.x;
    const int warp = tid >> 5, lane = tid & 31;
    const int g    = lane >> 2, tq  = lane & 3;
    const int wm   = (warp & 1) * 64;          // warp grid 2 (m) x 4 (n)
    const int wn   = (warp >> 1) * 32;

    if (tid < BM) {
        int r = m_base + tid;
        sTok[tid]  = (r < cnt) ? g_tok[e * T + r]  : 0;
        sGate[tid] = (r < cnt) ? g_gate[e * T + r] : 0.0f;
    }

    float cc[4][4][4];
#pragma unroll
    for (int a = 0; a < 4; a++)
#pragma unroll
        for (int b = 0; b < 4; b++)
#pragma unroll
            for (int c = 0; c < 4; c++) cc[a][b][c] = 0.0f;

    const float* hb = g_h + (size_t)e * T * HM;
    const float* wB = Wd + (size_t)e * HM * DM + n_base;

    auto load_tiles = [&](int st, int k0) {
        // A: 128 x 16 (slot rows, zero-filled beyond cnt) -> 512 float4
#pragma unroll
        for (int j = 0; j < 2; j++) {
            int idx = tid + j * 256;
            int row = idx >> 2;
            int c4  = (idx & 3) << 2;
            bool v  = (m_base + row) < cnt;
            cp16(&sA[st][row][c4], hb + (size_t)(m_base + row) * HM + k0 + c4, v);
        }
        // B: 16 x 128 -> 512 float4
#pragma unroll
        for (int j = 0; j < 2; j++) {
            int idx = tid + j * 256;
            int kr  = idx >> 5;
            int c4  = (idx & 31) << 2;
            cp16(&sB[st][kr][c4], wB + (size_t)(k0 + kr) * DM + c4, true);
        }
        cp_commit();
    };

    load_tiles(0, 0);
    const int KT = HM / BK;   // 256
    for (int kt = 0; kt < KT; kt++) {
        int cur = kt & 1;
        if (kt + 1 < KT) { load_tiles(cur ^ 1, (kt + 1) * BK); cp_wait<1>(); }
        else             { cp_wait<0>(); }
        __syncthreads();

#pragma unroll
        for (int kk = 0; kk < BK; kk += 8) {
            uint32_t af[4][4];
#pragma unroll
            for (int im = 0; im < 4; im++) {
                int r = wm + im * 16 + g;
                af[im][0] = __float_as_uint(sA[cur][r    ][kk + tq    ]);
                af[im][1] = __float_as_uint(sA[cur][r + 8][kk + tq    ]);
                af[im][2] = __float_as_uint(sA[cur][r    ][kk + tq + 4]);
                af[im][3] = __float_as_uint(sA[cur][r + 8][kk + tq + 4]);
            }
#pragma unroll
            for (int in = 0; in < 4; in++) {
                int c = wn + in * 8 + g;
                uint32_t bf[2] = { f2tf32(sB[cur][kk + tq][c]), f2tf32(sB[cur][kk + tq + 4][c]) };
#pragma unroll
                for (int im = 0; im < 4; im++)
                    mma_tf32(cc[im][in], af[im], bf);
            }
        }
        __syncthreads();
    }

    // epilogue: scatter-accumulate to out[token] with gate weight
    const float* bde = bd + (size_t)e * DM;
#pragma unroll
    for (int im = 0; im < 4; im++) {
        int rl = wm + im * 16 + g;       // local row
        int rg = m_base + rl;            // global slot row
#pragma unroll
        for (int in = 0; in < 4; in++) {
            int n = n_base + wn + in * 8 + tq * 2;
            float b0 = bde[n], b1 = bde[n + 1];
            if (rg < cnt) {
                int   t  = sTok[rl];
                float gt = sGate[rl];
                atomicAdd(&out[(size_t)t * DM + n    ], gt * (cc[im][in][0] + b0));
                atomicAdd(&out[(size_t)t * DM + n + 1], gt * (cc[im][in][1] + b1));
            }
            if (rg + 8 < cnt) {
                int   t  = sTok[rl + 8];
                float gt = sGate[rl + 8];
                atomicAdd(&out[(size_t)t * DM + n    ], gt * (cc[im][in][2] + b0));
                atomicAdd(&out[(size_t)t * DM + n + 1], gt * (cc[im][in][3] + b1));
            }
        }
    }
}

// ---------------------------------------------------------------------------
extern "C" void kernel_launch(void* const* d_in, const int* in_sizes, int n_in,
                              void* d_out, int out_size) {
    const float* x  = (const float*)d_in[0];
    const float* Wr = (const float*)d_in[1];
    const float* br = (const float*)d_in[2];
    const float* Wg = (const float*)d_in[3];
    const float* bg = (const float*)d_in[4];
    const float* Wu = (const float*)d_in[5];
    const float* bu = (const float*)d_in[6];
    const float* Wd = (const float*)d_in[7];
    const float* bd = (const float*)d_in[8];
    float* out = (float*)d_out;

    int n_out = T * DM;
    k_zero<<<(n_out + 255) / 256, 256>>>(out, n_out);
    k_router<<<T / 8, 256>>>(x, Wr, br);

    dim3 g1(T / BM, HM / BN, EM);
    k_ffn1<<<g1, 256>>>(x, Wg, bg, Wu, bu);

    dim3 g2(T / BM, DM / BN2, EM);
    k_ffn2<<<g2, 256>>>(Wd, bd, out);
}

// round 8
// speedup vs baseline: 2.1794x; 2.1794x over previous
#include <cuda_runtime.h>
#include <cuda_fp16.h>
#include <math.h>
#include <stdint.h>

// Problem constants
#define T  8192
#define DM 1024
#define EM 8
#define HM 4096

// Tiling: BM=128, 128 smem cols (fp16), BK=32, 8 warps (2x4), warp tile 64x32
#define BM 128
#define BK 32
#define ASTRH 40     // sA row stride in halves (80B) -> conflict-free ldmatrix
#define BSTRH 136    // sB row stride in halves (272B) -> conflict-free ldmatrix

// Device scratch
__device__ int    g_count[EM];
__device__ int    g_tok[EM * T];
__device__ float  g_gate[EM * T];
__device__ __half g_xh[T * DM];          // fp16 x
__device__ __half g_wgh[EM * DM * HM];   // fp16 weights (same [k][n] layout)
__device__ __half g_wuh[EM * DM * HM];
__device__ __half g_wdh[EM * HM * DM];
__device__ __half g_hh[EM * T * HM];     // fp16 hidden activations

// ---------------------------------------------------------------------------
// helpers
// ---------------------------------------------------------------------------
__device__ __forceinline__ void mma_f16(float d[4], const uint32_t a[4], const uint32_t b[2]) {
    asm volatile(
        "mma.sync.aligned.m16n8k16.row.col.f32.f16.f16.f32 "
        "{%0,%1,%2,%3}, {%4,%5,%6,%7}, {%8,%9}, {%0,%1,%2,%3};"
        : "+f"(d[0]), "+f"(d[1]), "+f"(d[2]), "+f"(d[3])
        : "r"(a[0]), "r"(a[1]), "r"(a[2]), "r"(a[3]),
          "r"(b[0]), "r"(b[1]));
}

__device__ __forceinline__ void ldsm4(uint32_t& r0, uint32_t& r1, uint32_t& r2, uint32_t& r3,
                                      uint32_t saddr) {
    asm volatile("ldmatrix.sync.aligned.m8n8.x4.shared.b16 {%0,%1,%2,%3}, [%4];"
                 : "=r"(r0), "=r"(r1), "=r"(r2), "=r"(r3) : "r"(saddr));
}
__device__ __forceinline__ void ldsm4t(uint32_t& r0, uint32_t& r1, uint32_t& r2, uint32_t& r3,
                                       uint32_t saddr) {
    asm volatile("ldmatrix.sync.aligned.m8n8.x4.trans.shared.b16 {%0,%1,%2,%3}, [%4];"
                 : "=r"(r0), "=r"(r1), "=r"(r2), "=r"(r3) : "r"(saddr));
}

__device__ __forceinline__ void cp16(void* smem_ptr, const void* gptr, bool valid) {
    uint32_t sa = (uint32_t)__cvta_generic_to_shared(smem_ptr);
    int sz = valid ? 16 : 0;
    asm volatile("cp.async.cg.shared.global [%0], [%1], 16, %2;"
                 :: "r"(sa), "l"(gptr), "r"(sz));
}
__device__ __forceinline__ void cp_commit() { asm volatile("cp.async.commit_group;"); }
template <int N>
__device__ __forceinline__ void cp_wait() { asm volatile("cp.async.wait_group %0;" :: "n"(N)); }

// ---------------------------------------------------------------------------
// prep: zero out + convert x to fp16 + zero counters
// ---------------------------------------------------------------------------
__global__ void k_prep(float4* __restrict__ out, const float4* __restrict__ x, int n4) {
    int i = blockIdx.x * blockDim.x + threadIdx.x;
    if (i < n4) {
        out[i] = make_float4(0.f, 0.f, 0.f, 0.f);
        float4 v = x[i];
        ((__half2*)g_xh)[2 * i    ] = __floats2half2_rn(v.x, v.y);
        ((__half2*)g_xh)[2 * i + 1] = __floats2half2_rn(v.z, v.w);
    }
    if (i < EM) g_count[i] = 0;
}

// convert a weight tensor fp32 -> fp16
__global__ void k_cvt(const float4* __restrict__ src, __half2* __restrict__ dst, int n4) {
    int i = blockIdx.x * blockDim.x + threadIdx.x;
    if (i < n4) {
        float4 v = src[i];
        dst[2 * i    ] = __floats2half2_rn(v.x, v.y);
        dst[2 * i + 1] = __floats2half2_rn(v.z, v.w);
    }
}

// ---------------------------------------------------------------------------
// router: one warp per token (fp32, unchanged)
// ---------------------------------------------------------------------------
__global__ void k_router(const float* __restrict__ x,
                         const float* __restrict__ Wr,
                         const float* __restrict__ br) {
    int t    = blockIdx.x * (blockDim.x >> 5) + (threadIdx.x >> 5);
    int lane = threadIdx.x & 31;
    if (t >= T) return;

    const float* xr = x + (size_t)t * DM;
    float acc[EM];
#pragma unroll
    for (int e = 0; e < EM; e++) acc[e] = 0.0f;

    for (int d = lane; d < DM; d += 32) {
        float xv = xr[d];
        const float4 w0 = *(const float4*)(Wr + (size_t)d * EM);
        const float4 w1 = *(const float4*)(Wr + (size_t)d * EM + 4);
        acc[0] += xv * w0.x; acc[1] += xv * w0.y;
        acc[2] += xv * w0.z; acc[3] += xv * w0.w;
        acc[4] += xv * w1.x; acc[5] += xv * w1.y;
        acc[6] += xv * w1.z; acc[7] += xv * w1.w;
    }
#pragma unroll
    for (int e = 0; e < EM; e++) {
#pragma unroll
        for (int o = 16; o > 0; o >>= 1)
            acc[e] += __shfl_xor_sync(0xffffffffu, acc[e], o);
    }

    if (lane == 0) {
        float v[EM];
#pragma unroll
        for (int e = 0; e < EM; e++) v[e] = acc[e] + br[e];

        int b0 = 0; float m0 = v[0];
#pragma unroll
        for (int e = 1; e < EM; e++) if (v[e] > m0) { m0 = v[e]; b0 = e; }
        int b1 = -1; float m1 = -3.4e38f;
#pragma unroll
        for (int e = 0; e < EM; e++) {
            if (e == b0) continue;
            if (v[e] > m1) { m1 = v[e]; b1 = e; }
        }
        float p0 = 1.0f / (1.0f + expf(m1 - m0));
        float p1 = 1.0f - p0;

        int pos = atomicAdd(&g_count[b0], 1);
        g_tok[b0 * T + pos] = t;  g_gate[b0 * T + pos] = p0;
        pos = atomicAdd(&g_count[b1], 1);
        g_tok[b1 * T + pos] = t;  g_gate[b1 * T + pos] = p1;
    }
}

// ---------------------------------------------------------------------------
// fp16 gemm step: one BK=32 k-tile = 2 kk-steps of k16
// A via ldmatrix.x4, B via ldmatrix.x4.trans, m16n8k16 f16 MMA
// ---------------------------------------------------------------------------
__device__ __forceinline__ void gemm_step_f16(
    uint32_t sa_base, uint32_t sb_base,   // smem addrs of current A/B stages
    int wm, int wn, int lane, float cc[4][4][4]) {

    const int mid = lane >> 3, mr = lane & 7;
    const int arow = (mid & 1) * 8 + mr;        // row within 16-row block
    const int akoff = (mid >> 1) * 8;           // k offset 0/8
    const int bkrow = (mid & 1) * 8 + mr;       // k row within 16
    const int bcoff = (mid >> 1) * 8;           // n offset 0/8

#pragma unroll
    for (int kk = 0; kk < BK; kk += 16) {
        uint32_t af[4][4];
#pragma unroll
        for (int im = 0; im < 4; im++) {
            uint32_t addr = sa_base + ((wm + im * 16 + arow) * ASTRH + kk + akoff) * 2;
            ldsm4(af[im][0], af[im][1], af[im][2], af[im][3], addr);
        }
        uint32_t bf[4][2];
#pragma unroll
        for (int inp = 0; inp < 2; inp++) {
            uint32_t addr = sb_base + ((kk + bkrow) * BSTRH + wn + inp * 16 + bcoff) * 2;
            uint32_t r0, r1, r2, r3;
            ldsm4t(r0, r1, r2, r3, addr);
            bf[2 * inp    ][0] = r0; bf[2 * inp    ][1] = r1;
            bf[2 * inp + 1][0] = r2; bf[2 * inp + 1][1] = r3;
        }
#pragma unroll
        for (int in = 0; in < 4; in++)
#pragma unroll
            for (int im = 0; im < 4; im++)
                mma_f16(cc[im][in], af[im], bf[in]);
    }
}

// ---------------------------------------------------------------------------
// phase 1: h = silu(x@Wg+bg) * (x@Wu+bu), fp16 MMA
// B tile: 128 cols = 16 n8-blocks, even block -> Wg, odd -> Wu (same h cols)
// grid: (T/BM, HM/64, EM), 256 threads, 2-stage cp.async
// ---------------------------------------------------------------------------
__global__ __launch_bounds__(256) void k_ffn1(
    const float* __restrict__ bg, const float* __restrict__ bu) {

    const int e      = blockIdx.z;
    const int cnt    = g_count[e];
    const int m_base = blockIdx.x * BM;
    if (m_base >= cnt) return;
    const int n_base = blockIdx.y * 64;   // logical H columns

    __shared__ __align__(16) __half sA[2][BM][ASTRH];
    __shared__ __align__(16) __half sB[2][BK][BSTRH];
    __shared__ int sTok[BM];

    const int tid  = threadIdx.x;
    const int warp = tid >> 5, lane = tid & 31;
    const int g    = lane >> 2, tq  = lane & 3;
    const int wm   = (warp & 1) * 64;
    const int wn   = (warp >> 1) * 32;

    if (tid < BM) {
        int r = m_base + tid;
        sTok[tid] = (r < cnt) ? g_tok[e * T + r] : 0;
    }
    __syncthreads();

    float cc[4][4][4];
#pragma unroll
    for (int a = 0; a < 4; a++)
#pragma unroll
        for (int b = 0; b < 4; b++)
#pragma unroll
            for (int c = 0; c < 4; c++) cc[a][b][c] = 0.0f;

    const __half* wg = g_wgh + (size_t)e * DM * HM + n_base;
    const __half* wu = g_wuh + (size_t)e * DM * HM + n_base;

    auto load_tiles = [&](int st, int k0) {
#pragma unroll
        for (int j = 0; j < 2; j++) {          // A: 128 rows x 32 halves (4 chunks/row)
            int idx = tid + j * 256;
            int row = idx >> 2;
            int c8  = (idx & 3) << 3;
            cp16(&sA[st][row][c8], g_xh + (size_t)sTok[row] * DM + k0 + c8, true);
        }
#pragma unroll
        for (int j = 0; j < 2; j++) {          // B: 32 rows x 128 halves (16 chunks/row)
            int idx = tid + j * 256;
            int kr  = idx >> 4;
            int q   = idx & 15;                // n8 block: even=Wg, odd=Wu
            const __half* src = (q & 1) ? wu : wg;
            cp16(&sB[st][kr][q << 3], src + (size_t)(k0 + kr) * HM + ((q >> 1) << 3), true);
        }
        cp_commit();
    };

    uint32_t sa0 = (uint32_t)__cvta_generic_to_shared(&sA[0][0][0]);
    uint32_t sb0 = (uint32_t)__cvta_generic_to_shared(&sB[0][0][0]);
    const uint32_t saSz = BM * ASTRH * 2, sbSz = BK * BSTRH * 2;

    load_tiles(0, 0);
    const int KT = DM / BK;   // 32
    for (int kt = 0; kt < KT; kt++) {
        int cur = kt & 1;
        if (kt + 1 < KT) { load_tiles(cur ^ 1, (kt + 1) * BK); cp_wait<1>(); }
        else             { cp_wait<0>(); }
        __syncthreads();
        gemm_step_f16(sa0 + cur * saSz, sb0 + cur * sbSz, wm, wn, lane, cc);
        __syncthreads();
    }

    // epilogue: in=2j -> gate, in=2j+1 -> up, same logical cols. Pure-register silu.
    const float* bge = bg + (size_t)e * HM;
    const float* bue = bu + (size_t)e * HM;
    __half* hb = g_hh + (size_t)e * T * HM;
#pragma unroll
    for (int im = 0; im < 4; im++) {
        int r0 = m_base + wm + im * 16 + g;
#pragma unroll
        for (int j = 0; j < 2; j++) {
            int L  = n_base + ((wn >> 4) + j) * 8;   // logical col block
            int c0 = L + 2 * tq;
            float bg0 = bge[c0], bg1 = bge[c0 + 1];
            float bu0 = bue[c0], bu1 = bue[c0 + 1];
            if (r0 < cnt) {
                float gv0 = cc[im][2 * j][0] + bg0, gv1 = cc[im][2 * j][1] + bg1;
                float uv0 = cc[im][2 * j + 1][0] + bu0, uv1 = cc[im][2 * j + 1][1] + bu1;
                *(__half2*)(hb + (size_t)r0 * HM + c0) = __floats2half2_rn(
                    gv0 / (1.0f + expf(-gv0)) * uv0,
                    gv1 / (1.0f + expf(-gv1)) * uv1);
            }
            if (r0 + 8 < cnt) {
                float gv0 = cc[im][2 * j][2] + bg0, gv1 = cc[im][2 * j][3] + bg1;
                float uv0 = cc[im][2 * j + 1][2] + bu0, uv1 = cc[im][2 * j + 1][3] + bu1;
                *(__half2*)(hb + (size_t)(r0 + 8) * HM + c0) = __floats2half2_rn(
                    gv0 / (1.0f + expf(-gv0)) * uv0,
                    gv1 / (1.0f + expf(-gv1)) * uv1);
            }
        }
    }
}

// ---------------------------------------------------------------------------
// phase 2: out[tok] += gate * (h @ Wd + bd), fp16 MMA
// grid: (T/BM, DM/128, EM), 256 threads, 2-stage cp.async
// ---------------------------------------------------------------------------
__global__ __launch_bounds__(256) void k_ffn2(
    const float* __restrict__ bd, float* __restrict__ out) {

    const int e      = blockIdx.z;
    const int cnt    = g_count[e];
    const int m_base = blockIdx.x * BM;
    if (m_base >= cnt) return;
    const int n_base = blockIdx.y * 128;

    __shared__ __align__(16) __half sA[2][BM][ASTRH];
    __shared__ __align__(16) __half sB[2][BK][BSTRH];
    __shared__ int   sTok[BM];
    __shared__ float sGate[BM];

    const int tid  = threadIdx.x;
    const int warp = tid >> 5, lane = tid & 31;
    const int g    = lane >> 2, tq  = lane & 3;
    const int wm   = (warp & 1) * 64;
    const int wn   = (warp >> 1) * 32;

    if (tid < BM) {
        int r = m_base + tid;
        sTok[tid]  = (r < cnt) ? g_tok[e * T + r]  : 0;
        sGate[tid] = (r < cnt) ? g_gate[e * T + r] : 0.0f;
    }

    float cc[4][4][4];
#pragma unroll
    for (int a = 0; a < 4; a++)
#pragma unroll
        for (int b = 0; b < 4; b++)
#pragma unroll
            for (int c = 0; c < 4; c++) cc[a][b][c] = 0.0f;

    const __half* hb = g_hh + (size_t)e * T * HM;
    const __half* wd = g_wdh + (size_t)e * HM * DM + n_base;

    auto load_tiles = [&](int st, int k0) {
#pragma unroll
        for (int j = 0; j < 2; j++) {          // A: 128 slot rows x 32 halves (zfill)
            int idx = tid + j * 256;
            int row = idx >> 2;
            int c8  = (idx & 3) << 3;
            bool v  = (m_base + row) < cnt;
            cp16(&sA[st][row][c8], hb + (size_t)(m_base + row) * HM + k0 + c8, v);
        }
#pragma unroll
        for (int j = 0; j < 2; j++) {          // B: 32 rows x 128 halves
            int idx = tid + j * 256;
            int kr  = idx >> 4;
            int c8  = (idx & 15) << 3;
            cp16(&sB[st][kr][c8], wd + (size_t)(k0 + kr) * DM + c8, true);
        }
        cp_commit();
    };

    uint32_t sa0 = (uint32_t)__cvta_generic_to_shared(&sA[0][0][0]);
    uint32_t sb0 = (uint32_t)__cvta_generic_to_shared(&sB[0][0][0]);
    const uint32_t saSz = BM * ASTRH * 2, sbSz = BK * BSTRH * 2;

    load_tiles(0, 0);
    const int KT = HM / BK;   // 128
    for (int kt = 0; kt < KT; kt++) {
        int cur = kt & 1;
        if (kt + 1 < KT) { load_tiles(cur ^ 1, (kt + 1) * BK); cp_wait<1>(); }
        else             { cp_wait<0>(); }
        __syncthreads();
        gemm_step_f16(sa0 + cur * saSz, sb0 + cur * sbSz, wm, wn, lane, cc);
        __syncthreads();
    }

    // epilogue: gate-weighted scatter atomicAdd
    const float* bde = bd + (size_t)e * DM;
#pragma unroll
    for (int im = 0; im < 4; im++) {
        int rl = wm + im * 16 + g;
        int rg = m_base + rl;
#pragma unroll
        for (int in = 0; in < 4; in++) {
            int n = n_base + wn + in * 8 + tq * 2;
            float b0 = bde[n], b1 = bde[n + 1];
            if (rg < cnt) {
                int   t  = sTok[rl];
                float gt = sGate[rl];
                atomicAdd(&out[(size_t)t * DM + n    ], gt * (cc[im][in][0] + b0));
                atomicAdd(&out[(size_t)t * DM + n + 1], gt * (cc[im][in][1] + b1));
            }
            if (rg + 8 < cnt) {
                int   t  = sTok[rl + 8];
                float gt = sGate[rl + 8];
                atomicAdd(&out[(size_t)t * DM + n    ], gt * (cc[im][in][2] + b0));
                atomicAdd(&out[(size_t)t * DM + n + 1], gt * (cc[im][in][3] + b1));
            }
        }
    }
}

// ---------------------------------------------------------------------------
extern "C" void kernel_launch(void* const* d_in, const int* in_sizes, int n_in,
                              void* d_out, int out_size) {
    const float* x  = (const float*)d_in[0];
    const float* Wr = (const float*)d_in[1];
    const float* br = (const float*)d_in[2];
    const float* Wg = (const float*)d_in[3];
    const float* bg = (const float*)d_in[4];
    const float* Wu = (const float*)d_in[5];
    const float* bu = (const float*)d_in[6];
    const float* Wd = (const float*)d_in[7];
    const float* bd = (const float*)d_in[8];
    float* out = (float*)d_out;

    __half *wgh, *wuh, *wdh;
    cudaGetSymbolAddress((void**)&wgh, g_wgh);
    cudaGetSymbolAddress((void**)&wuh, g_wuh);
    cudaGetSymbolAddress((void**)&wdh, g_wdh);

    int n4x = T * DM / 4;
    k_prep<<<(n4x + 255) / 256, 256>>>((float4*)out, (const float4*)x, n4x);

    int n4w = EM * DM * HM / 4;
    k_cvt<<<(n4w + 255) / 256, 256>>>((const float4*)Wg, (__half2*)wgh, n4w);
    k_cvt<<<(n4w + 255) / 256, 256>>>((const float4*)Wu, (__half2*)wuh, n4w);
    k_cvt<<<(n4w + 255) / 256, 256>>>((const float4*)Wd, (__half2*)wdh, n4w);

    k_router<<<T / 8, 256>>>(x, Wr, br);

    dim3 g1(T / BM, HM / 64, EM);
    k_ffn1<<<g1, 256>>>(bg, bu);

    dim3 g2(T / BM, DM / 128, EM);
    k_ffn2<<<g2, 256>>>(bd, out);
}